// round 8
// baseline (speedup 1.0000x reference)
#include <cuda_runtime.h>

#define B_ 4
#define S_ 2048
#define E_ 1024
#define A_ 128
#define M_ (B_*S_)   // 8192

typedef unsigned long long u64;

// ---- packed fp32x2 helpers (SASS FFMA2 path; ptxas never emits these from C++) ----
__device__ __forceinline__ void ffma2(u64& d, u64 a, u64 b) {
    asm("fma.rn.f32x2 %0, %1, %2, %0;" : "+l"(d) : "l"(a), "l"(b));
}
__device__ __forceinline__ void fmul2(u64& d, u64 a) {
    asm("mul.rn.f32x2 %0, %0, %1;" : "+l"(d) : "l"(a));
}
__device__ __forceinline__ u64 pack2(float lo, float hi) {
    u64 r;
    asm("mov.b64 %0, {%1, %2};" : "=l"(r)
        : "r"(__float_as_uint(lo)), "r"(__float_as_uint(hi)));
    return r;
}
__device__ __forceinline__ void unpack2(u64 p, float& lo, float& hi) {
    unsigned ulo, uhi;
    asm("mov.b64 {%0, %1}, %2;" : "=r"(ulo), "=r"(uhi) : "l"(p));
    lo = __uint_as_float(ulo); hi = __uint_as_float(uhi);
}
__device__ __forceinline__ u64 swap2(u64 p) {
    float lo, hi; unpack2(p, lo, hi); return pack2(hi, lo);
}

// scratch (device globals: no allocation allowed)
__device__ float g_q [M_*A_];        // [b][s][a], pre-scaled by 1/sqrt(A)
__device__ float g_kt[B_*A_*S_];     // [b][a][s]  (K transposed)
__device__ float g_v [M_*A_];        // [b][s][a]

// ---------------------------------------------------------------------------
// Projection with FFMA2: y[m][n] = sum_e x[m][e] * W[n][e]
// grid (128, 3). block 256 = 32c x 8r. micro: 8 rows (4 f32x2 row-pairs) x 4 cols.
// x staged TRANSPOSED (xs_t[kk][row]) so row-pairs load as ulonglong2.
// B (ws) stays [n][kk] pitch 33; scalar loads dup-packed per column.
// ---------------------------------------------------------------------------
#define KT 32
#define XTP 68   // xs_t pitch (floats); 68*4=272 bytes, 16B-aligned rows

__global__ __launch_bounds__(256) void proj_kernel(
    const float* __restrict__ x,
    const float* __restrict__ Wk,
    const float* __restrict__ Wq,
    const float* __restrict__ Wv)
{
    const int which = blockIdx.y;               // 0=K, 1=Q, 2=V
    const float* __restrict__ W = (which == 0) ? Wk : ((which == 1) ? Wq : Wv);
    const int m0  = blockIdx.x * 64;
    const int tid = threadIdx.x;
    const int c   = tid & 31;
    const int r   = tid >> 5;

    __shared__ float xs_t[KT * XTP];     // [kk][row]
    __shared__ float ws[128 * 33];       // [n][kk]

    u64 acc[4][4];
#pragma unroll
    for (int p = 0; p < 4; p++)
#pragma unroll
        for (int j = 0; j < 4; j++) acc[p][j] = 0ull;

    const int xrow = tid >> 2;            // 0..63
    const int xcb  = (tid & 3) * 8;       // 0,8,16,24
    const int wrow = tid >> 1;            // 0..127
    const int wcb  = (tid & 1) * 16;      // 0,16

    for (int kt = 0; kt < E_; kt += KT) {
        // stage gmem -> regs
        float4 xa = *(const float4*)&x[(m0 + xrow) * E_ + kt + xcb];
        float4 xb = *(const float4*)&x[(m0 + xrow) * E_ + kt + xcb + 4];
        float4 w0 = *(const float4*)&W[wrow * E_ + kt + wcb];
        float4 w1 = *(const float4*)&W[wrow * E_ + kt + wcb + 4];
        float4 w2 = *(const float4*)&W[wrow * E_ + kt + wcb + 8];
        float4 w3 = *(const float4*)&W[wrow * E_ + kt + wcb + 12];

        __syncthreads();   // previous compute done
        {
            float xv[8] = {xa.x, xa.y, xa.z, xa.w, xb.x, xb.y, xb.z, xb.w};
#pragma unroll
            for (int u = 0; u < 8; u++)
                xs_t[(xcb + u) * XTP + xrow] = xv[u];  // transpose
            float* pw = &ws[wrow * 33 + wcb];
            pw[0]=w0.x; pw[1]=w0.y; pw[2]=w0.z; pw[3]=w0.w;
            pw[4]=w1.x; pw[5]=w1.y; pw[6]=w1.z; pw[7]=w1.w;
            pw[8]=w2.x; pw[9]=w2.y; pw[10]=w2.z; pw[11]=w2.w;
            pw[12]=w3.x; pw[13]=w3.y; pw[14]=w3.z; pw[15]=w3.w;
        }
        __syncthreads();   // smem ready

#pragma unroll 4
        for (int kk = 0; kk < KT; kk++) {
            const float* xt = &xs_t[kk * XTP + r * 8];
            ulonglong2 av0 = *(const ulonglong2*)xt;        // row-pairs (0,1),(2,3)
            ulonglong2 av1 = *(const ulonglong2*)(xt + 4);  // row-pairs (4,5),(6,7)
            u64 B0 = pack2(ws[(c      ) * 33 + kk], ws[(c      ) * 33 + kk]);
            u64 B1 = pack2(ws[(c + 32 ) * 33 + kk], ws[(c + 32 ) * 33 + kk]);
            u64 B2 = pack2(ws[(c + 64 ) * 33 + kk], ws[(c + 64 ) * 33 + kk]);
            u64 B3 = pack2(ws[(c + 96 ) * 33 + kk], ws[(c + 96 ) * 33 + kk]);
            ffma2(acc[0][0], av0.x, B0); ffma2(acc[0][1], av0.x, B1);
            ffma2(acc[0][2], av0.x, B2); ffma2(acc[0][3], av0.x, B3);
            ffma2(acc[1][0], av0.y, B0); ffma2(acc[1][1], av0.y, B1);
            ffma2(acc[1][2], av0.y, B2); ffma2(acc[1][3], av0.y, B3);
            ffma2(acc[2][0], av1.x, B0); ffma2(acc[2][1], av1.x, B1);
            ffma2(acc[2][2], av1.x, B2); ffma2(acc[2][3], av1.x, B3);
            ffma2(acc[3][0], av1.y, B0); ffma2(acc[3][1], av1.y, B1);
            ffma2(acc[3][2], av1.y, B2); ffma2(acc[3][3], av1.y, B3);
        }
    }

    const float qscale = 0.08838834764831843f;  // 1/sqrt(128)
#pragma unroll
    for (int p = 0; p < 4; p++) {
#pragma unroll
        for (int j = 0; j < 4; j++) {
            float vA, vB; unpack2(acc[p][j], vA, vB);
            const int n = c + 32 * j;
#pragma unroll
            for (int h = 0; h < 2; h++) {
                const int m = m0 + r * 8 + 2 * p + h;
                float v = h ? vB : vA;
                if (which == 1) {
                    g_q[m * A_ + n] = v * qscale;
                } else if (which == 2) {
                    g_v[m * A_ + n] = v;
                } else {
                    const int bb = m >> 11;
                    const int s  = m & (S_ - 1);
                    g_kt[(bb * A_ + n) * S_ + s] = v;
                }
            }
        }
    }
}

// ---------------------------------------------------------------------------
// Flash attention (causal), fp32 via FFMA2.
// BM=32, BN=128. grid (64,4) longest-first. block 256.
// Warp-pair column split: warp w owns cols (w&1)*64..+63, rows (w>>2... rg=w>>1)*8..+7.
// lane l: rh=l>>4 -> rows rowbase..rowbase+3; cols cl..cl+3.
// Q and P stored transposed ([d][row] / [key][row]) -> row-pairs are natural
// ulonglong2; swap-trick 2x2 blocks avoid dup-packing.
// Softmax: 16-lane shfl + cross-warp smem combine.
// ---------------------------------------------------------------------------
#define BM 32
#define BN 128
#define QP 132   // k_s/v_s pitch (floats)
#define TP 36    // q_t/p_t pitch (floats); 144 bytes, 16B-aligned rows

// q_t[128][36] + k_s[128][132] + v_s[128][132] + p_t[128][36]
#define ATTN_SMEM ((36 + 132 + 132 + 36) * 128 * 4)

__global__ __launch_bounds__(256, 1) void attn_kernel(float* __restrict__ out)
{
    extern __shared__ float sm[];
    float* q_t = sm;                    // [128][TP]   q_t[d][row]
    float* k_s = q_t + 128 * TP;        // [128][QP]   k_s[d][key]
    float* v_s = k_s + 128 * QP;        // [128][QP]   v_s[key][d]
    float* p_t = v_s + 128 * QP;        // [128][TP]   p_t[key][row]
    __shared__ float red_m[2][32];
    __shared__ float red_s[2][32];

    const int qt  = 63 - blockIdx.x;    // longest CTAs first
    const int b   = blockIdx.y;
    const int q0  = qt * BM;
    const int tid = threadIdx.x;
    const int w   = tid >> 5;
    const int l   = tid & 31;

    const int half    = w & 1;              // column half
    const int rg      = w >> 1;             // 0..3
    const int rh      = l >> 4;             // 0..1
    const int rowbase = rg * 8 + rh * 4;    // rows rowbase..rowbase+3
    const int cl      = half * 64 + (l & 15) * 4;  // cols cl..cl+3

    // stage Q transposed: q_t[d][row]
    {
        const int row = tid >> 3;              // 0..31
        const int cb  = (tid & 7) * 16;        // 0..112
        const float* gq = &g_q[(b * S_ + q0 + row) * A_ + cb];
#pragma unroll
        for (int u = 0; u < 4; u++) {
            float4 qv = *(const float4*)(gq + u * 4);
            q_t[(cb + u * 4 + 0) * TP + row] = qv.x;
            q_t[(cb + u * 4 + 1) * TP + row] = qv.y;
            q_t[(cb + u * 4 + 2) * TP + row] = qv.z;
            q_t[(cb + u * 4 + 3) * TP + row] = qv.w;
        }
    }

    float m_i[4], l_i[4];
    u64 o2[2][2][2];
#pragma unroll
    for (int i = 0; i < 4; i++) { m_i[i] = -1e30f; l_i[i] = 0.f; }
#pragma unroll
    for (int rp = 0; rp < 2; rp++)
#pragma unroll
        for (int cp = 0; cp < 2; cp++) { o2[rp][cp][0] = 0ull; o2[rp][cp][1] = 0ull; }

    const int hrow = tid >> 1;                 // 0..127
    const int hcb  = (tid & 1) * 64;           // 0,64
    const int ntiles = (qt >> 2) + 1;

    for (int t = 0; t < ntiles; t++) {
        const int kb = t * BN;

        __syncthreads();   // Q/p_t consumed, prev PV done
        {
            const float* gk = &g_kt[(b * A_ + hrow) * S_ + kb + hcb];
            float* dk = &k_s[hrow * QP + hcb];
#pragma unroll
            for (int u = 0; u < 16; u++)
                *(float4*)(dk + u * 4) = *(const float4*)(gk + u * 4);
            const float* gv = &g_v[(b * S_ + kb + hrow) * A_ + hcb];
            float* dv = &v_s[hrow * QP + hcb];
#pragma unroll
            for (int u = 0; u < 16; u++)
                *(float4*)(dv + u * 4) = *(const float4*)(gv + u * 4);
        }
        __syncthreads();

        // ---- S = Q K^T, swap-trick 2x2 blocks (scrambled pairs) ----
        u64 s2[2][2][2];
#pragma unroll
        for (int rp = 0; rp < 2; rp++)
#pragma unroll
            for (int cp = 0; cp < 2; cp++) { s2[rp][cp][0] = 0ull; s2[rp][cp][1] = 0ull; }

#pragma unroll 4
        for (int kk = 0; kk < 128; kk++) {
            ulonglong2 aq = *(const ulonglong2*)&q_t[kk * TP + rowbase];
            ulonglong2 bk = *(const ulonglong2*)&k_s[kk * QP + cl];
            u64 b0s = swap2(bk.x);
            u64 b1s = swap2(bk.y);
            ffma2(s2[0][0][0], aq.x, bk.x);   // (r0c0, r1c1)
            ffma2(s2[0][0][1], aq.x, b0s);    // (r0c1, r1c0)
            ffma2(s2[0][1][0], aq.x, bk.y);
            ffma2(s2[0][1][1], aq.x, b1s);
            ffma2(s2[1][0][0], aq.y, bk.x);
            ffma2(s2[1][0][1], aq.y, b0s);
            ffma2(s2[1][1][0], aq.y, bk.y);
            ffma2(s2[1][1][1], aq.y, b1s);
        }

        // unscramble -> s[row 0..3][col 0..3]
        float s[4][4];
#pragma unroll
        for (int rp = 0; rp < 2; rp++)
#pragma unroll
            for (int cp = 0; cp < 2; cp++) {
                float a0, a1, b0, b1;
                unpack2(s2[rp][cp][0], a0, a1);
                unpack2(s2[rp][cp][1], b0, b1);
                s[2*rp  ][2*cp  ] = a0;
                s[2*rp+1][2*cp+1] = a1;
                s[2*rp  ][2*cp+1] = b0;
                s[2*rp+1][2*cp  ] = b1;
            }

        // causal mask (only the diagonal tile needs it)
        if (t == ntiles - 1) {
#pragma unroll
            for (int i = 0; i < 4; i++) {
                const int qg = q0 + rowbase + i;
#pragma unroll
                for (int j = 0; j < 4; j++)
                    if (kb + cl + j > qg) s[i][j] = -1e30f;
            }
        }

        // ---- online softmax with cross-warp combine ----
        float pm[4], al[4], ps[4], mnew[4], p[4][4];
#pragma unroll
        for (int i = 0; i < 4; i++) {
            float mx = fmaxf(fmaxf(s[i][0], s[i][1]), fmaxf(s[i][2], s[i][3]));
#pragma unroll
            for (int off = 8; off > 0; off >>= 1)
                mx = fmaxf(mx, __shfl_xor_sync(0xffffffffu, mx, off));
            pm[i] = mx;   // max over this warp's 64 keys
        }
        if ((l & 15) == 0) {
#pragma unroll
            for (int i = 0; i < 4; i++) red_m[half][rowbase + i] = pm[i];
        }
        __syncthreads();
#pragma unroll
        for (int i = 0; i < 4; i++) {
            const float om = red_m[half ^ 1][rowbase + i];
            mnew[i] = fmaxf(m_i[i], fmaxf(pm[i], om));
            al[i]   = __expf(m_i[i] - mnew[i]);
            p[i][0] = __expf(s[i][0] - mnew[i]);
            p[i][1] = __expf(s[i][1] - mnew[i]);
            p[i][2] = __expf(s[i][2] - mnew[i]);
            p[i][3] = __expf(s[i][3] - mnew[i]);
            float ss = (p[i][0] + p[i][1]) + (p[i][2] + p[i][3]);
#pragma unroll
            for (int off = 8; off > 0; off >>= 1)
                ss += __shfl_xor_sync(0xffffffffu, ss, off);
            ps[i] = ss;   // sum over this warp's 64 keys
            m_i[i] = mnew[i];
        }
        // write P transposed: p_t[key][row]
#pragma unroll
        for (int j = 0; j < 4; j++)
            *(float4*)&p_t[(cl + j) * TP + rowbase] =
                make_float4(p[0][j], p[1][j], p[2][j], p[3][j]);
        if ((l & 15) == 0) {
#pragma unroll
            for (int i = 0; i < 4; i++) red_s[half][rowbase + i] = ps[i];
        }
        // rescale O (halves of each pair are consecutive rows)
        {
            u64 a01 = pack2(al[0], al[1]);
            u64 a23 = pack2(al[2], al[3]);
#pragma unroll
            for (int cp = 0; cp < 2; cp++) {
                fmul2(o2[0][cp][0], a01); fmul2(o2[0][cp][1], a01);
                fmul2(o2[1][cp][0], a23); fmul2(o2[1][cp][1], a23);
            }
        }
        __syncthreads();   // p_t complete, red_s visible
#pragma unroll
        for (int i = 0; i < 4; i++)
            l_i[i] = l_i[i] * al[i] + ps[i] + red_s[half ^ 1][rowbase + i];

        // ---- O += P V (same swap-trick structure) ----
#pragma unroll 4
        for (int kk = 0; kk < 128; kk++) {
            ulonglong2 ap = *(const ulonglong2*)&p_t[kk * TP + rowbase];
            ulonglong2 bv = *(const ulonglong2*)&v_s[kk * QP + cl];
            u64 b0s = swap2(bv.x);
            u64 b1s = swap2(bv.y);
            ffma2(o2[0][0][0], ap.x, bv.x);
            ffma2(o2[0][0][1], ap.x, b0s);
            ffma2(o2[0][1][0], ap.x, bv.y);
            ffma2(o2[0][1][1], ap.x, b1s);
            ffma2(o2[1][0][0], ap.y, bv.x);
            ffma2(o2[1][0][1], ap.y, b0s);
            ffma2(o2[1][1][0], ap.y, bv.y);
            ffma2(o2[1][1][1], ap.y, b1s);
        }
    }

    // ---- epilogue: unscramble, normalize, store ----
    float o[4][4];
#pragma unroll
    for (int rp = 0; rp < 2; rp++)
#pragma unroll
        for (int cp = 0; cp < 2; cp++) {
            float a0, a1, b0, b1;
            unpack2(o2[rp][cp][0], a0, a1);
            unpack2(o2[rp][cp][1], b0, b1);
            o[2*rp  ][2*cp  ] = a0;
            o[2*rp+1][2*cp+1] = a1;
            o[2*rp  ][2*cp+1] = b0;
            o[2*rp+1][2*cp  ] = b1;
        }
#pragma unroll
    for (int i = 0; i < 4; i++) {
        const float inv = 1.f / l_i[i];
        float4 res;
        res.x = o[i][0] * inv;
        res.y = o[i][1] * inv;
        res.z = o[i][2] * inv;
        res.w = o[i][3] * inv;
        *(float4*)&out[(b * S_ + q0 + rowbase + i) * A_ + cl] = res;
    }
}

// ---------------------------------------------------------------------------
extern "C" void kernel_launch(void* const* d_in, const int* in_sizes, int n_in,
                              void* d_out, int out_size)
{
    const float* x  = (const float*)d_in[0];   // embedded [4,2048,1024]
    const float* Wk = (const float*)d_in[1];   // [128,1024]
    const float* Wq = (const float*)d_in[2];
    const float* Wv = (const float*)d_in[3];
    float* out = (float*)d_out;                // [4,2048,128] fp32

    cudaFuncSetAttribute(attn_kernel,
                         cudaFuncAttributeMaxDynamicSharedMemorySize,
                         ATTN_SMEM);

    proj_kernel<<<dim3(M_ / 64, 3), 256>>>(x, Wk, Wq, Wv);
    attn_kernel<<<dim3(64, B_), 256, ATTN_SMEM>>>(out);
}